// round 1
// baseline (speedup 1.0000x reference)
#include <cuda_runtime.h>
#include <cuda_bf16.h>

// MQCNN layer, closed form.
// Per output (b,j,k): 12 pixels from the 2x2 patch across 3 channels.
//   a  = x[b,0,2j,2k]   + x[b,1,2j,2k]   + x[b,2,2j,2k]
//   s1 = x[b,0,2j,2k+1] + x[b,1,2j+1,2k]
//   s2 = x[b,0,2j+1,2k] + x[b,2,2j+1,2k+1]
//   s3 = x[b,0,2j+1,2k+1]
//   s4 = x[b,1,2j,2k+1] + x[b,2,2j+1,2k]
//   s5 = x[b,1,2j+1,2k+1] + x[b,2,2j,2k+1]
// z = (6cos(a) + cos(a+s1)+cos(a+s2)+cos(a+s3)+cos(a+s4)+cos(a+s5)
//    + cos(a+s1+s3)+cos(a+s2+s5)+cos(a+s2+s3+s4)+cos(a+s1+s4+s5)
//    + cos(a+s1+s2+s3+s4+s5)) / 16
// The 24 controlled-U3 gates act on wire 6 only and cannot change the wire-4
// marginal; U3_w is mathematically irrelevant to the output.

#define B_DIM 32
#define H_OUT 64
#define W_OUT 64
#define N_OUT (B_DIM * H_OUT * W_OUT)
#define CH_STRIDE (128 * 128)

__global__ __launch_bounds__(256) void mqcnn_kernel(
    const float* __restrict__ x, float* __restrict__ out)
{
    int tid = blockIdx.x * blockDim.x + threadIdx.x;
    if (tid >= N_OUT) return;

    int k = tid & 63;
    int j = (tid >> 6) & 63;
    int b = tid >> 12;

    // pointer to x[b, 0, 2j, 2k]
    const float* base = x + (size_t)b * (3 * CH_STRIDE) + (size_t)(2 * j) * 128 + 2 * k;

    float2 c0r0 = *reinterpret_cast<const float2*>(base);
    float2 c0r1 = *reinterpret_cast<const float2*>(base + 128);
    float2 c1r0 = *reinterpret_cast<const float2*>(base + CH_STRIDE);
    float2 c1r1 = *reinterpret_cast<const float2*>(base + CH_STRIDE + 128);
    float2 c2r0 = *reinterpret_cast<const float2*>(base + 2 * CH_STRIDE);
    float2 c2r1 = *reinterpret_cast<const float2*>(base + 2 * CH_STRIDE + 128);

    float a  = c0r0.x + c1r0.x + c2r0.x;
    float s1 = c0r0.y + c1r1.x;
    float s2 = c0r1.x + c2r1.y;
    float s3 = c0r1.y;
    float s4 = c1r0.y + c2r1.x;
    float s5 = c1r1.y + c2r0.y;

    float sum = 6.0f * __cosf(a);
    sum += __cosf(a + s1);
    sum += __cosf(a + s2);
    sum += __cosf(a + s3);
    sum += __cosf(a + s4);
    sum += __cosf(a + s5);
    sum += __cosf(a + s1 + s3);
    sum += __cosf(a + s2 + s5);
    sum += __cosf(a + s2 + s3 + s4);
    sum += __cosf(a + s1 + s4 + s5);
    sum += __cosf(a + s1 + s2 + s3 + s4 + s5);

    out[tid] = sum * 0.0625f;
}

extern "C" void kernel_launch(void* const* d_in, const int* in_sizes, int n_in,
                              void* d_out, int out_size) {
    const float* x = (const float*)d_in[0];   // [32,3,128,128] float32
    // d_in[1] = U3_w: provably unused (unitary on wire 6 preserves wire-4 marginal)
    float* out = (float*)d_out;               // [32,1,64,64] float32

    mqcnn_kernel<<<N_OUT / 256, 256>>>(x, out);
}